// round 7
// baseline (speedup 1.0000x reference)
#include <cuda_runtime.h>
#include <cuda_fp16.h>
#include <math.h>

#define ATTN_OFF 262144          // B*1024 head elems, then attn [B,T,T]
#define GBLK 128                 // 128 blocks x 512 threads, 1 per SM

// ------------------- device globals (no allocation allowed) -------------------
__device__ __half g_UHh[33554432];         // [B*T, M] fp16  (67 MB)
__device__ __half g_Hh [33554432];         // fp16 copy of H (67 MB)
__device__ float  g_WdT[1024 * 512];       // W_d^T : [k=1024][col=512]
__device__ float  g_UdT[512 * 512];        // U_d^T : [m=512][n=512]
__device__ float  g_WT [1024 * 2048];      // [W_ih^T ; W_hh^T] : [k=1024][g=2048]
__device__ float  g_bias[2048];            // b_ih + b_hh
__device__ float  g_d  [131072];
__device__ float  g_s  [131072];
__device__ float  g_ct [131072];
__device__ float  g_gates[524288];         // raw gates [B, 4P]

__device__ unsigned g_bar_count = 0;
__device__ unsigned g_bar_gen   = 0;

// ------------------- helpers -------------------
__device__ __forceinline__ float tanh_fast(float x) {
    float y;
    asm("tanh.approx.f32 %0, %1;" : "=f"(y) : "f"(x));
    return y;
}
__device__ __forceinline__ float sigmoid_fast(float x) {
    return 1.f / (1.f + __expf(-x));
}
__device__ __forceinline__ unsigned long long pack2(float x) {
    unsigned long long r;
    asm("mov.b64 %0, {%1, %1};" : "=l"(r) : "f"(x));
    return r;
}
__device__ __forceinline__ void fma2(unsigned long long& d,
                                     unsigned long long a, unsigned long long b) {
    asm("fma.rn.f32x2 %0, %1, %2, %0;" : "+l"(d) : "l"(a), "l"(b));
}
__device__ __forceinline__ float2 unpack2(unsigned long long a) {
    float2 f;
    asm("mov.b64 {%0, %1}, %2;" : "=f"(f.x), "=f"(f.y) : "l"(a));
    return f;
}

// 8 fp16 terms: v[0..7] * tanh(uh[0..7] + wq[0..7])
__device__ __forceinline__ float row_term(uint4 u, const float* wq8, const float* v8) {
    float2 f0 = __half22float2(*(__half2*)&u.x);
    float2 f1 = __half22float2(*(__half2*)&u.y);
    float2 f2 = __half22float2(*(__half2*)&u.z);
    float2 f3 = __half22float2(*(__half2*)&u.w);
    float4 q0 = *(const float4*)&wq8[0];
    float4 q1 = *(const float4*)&wq8[4];
    float4 v0 = *(const float4*)&v8[0];
    float4 v1 = *(const float4*)&v8[4];
    float a;
    a  = v0.x * tanh_fast(f0.x + q0.x);
    a += v0.y * tanh_fast(f0.y + q0.y);
    a += v0.z * tanh_fast(f1.x + q0.z);
    a += v0.w * tanh_fast(f1.y + q0.w);
    a += v1.x * tanh_fast(f2.x + q1.x);
    a += v1.y * tanh_fast(f2.y + q1.y);
    a += v1.z * tanh_fast(f3.x + q1.z);
    a += v1.w * tanh_fast(f3.y + q1.w);
    return a;
}

// sense-reversing grid barrier
__device__ __forceinline__ void gsync() {
    __syncthreads();
    if (threadIdx.x == 0) {
        volatile unsigned* genp = (volatile unsigned*)&g_bar_gen;
        unsigned gen = *genp;
        __threadfence();
        if (atomicAdd(&g_bar_count, 1u) == (unsigned)(GBLK - 1)) {
            g_bar_count = 0;
            __threadfence();
            *genp = gen + 1;
        } else {
            while (*genp == gen) { }
            __threadfence();
        }
    }
    __syncthreads();
}

// ------------------- the single persistent kernel -------------------
__global__ void __launch_bounds__(512, 1)
k_decoder(const float* __restrict__ H,  const float* __restrict__ d0,
          const float* __restrict__ s0, const float* __restrict__ W_d,
          const float* __restrict__ U_d, const float* __restrict__ v_d,
          const float* __restrict__ W_ih, const float* __restrict__ W_hh,
          const float* __restrict__ b_ih, const float* __restrict__ b_hh,
          float* __restrict__ out) {
    // smem (48 KB), region use per phase:
    //  P1: [0..2047] q staging, [2048..6143] wq partials, [6144..7167] wqs out
    //  P2: [0..4127] redct, [4128..4639] vs, [4640..5151] es,
    //      [5152..5663] beta, [5664..5679] red8, [6144..7167] wqs (from P1)
    //  P3: [0..10239] q tile (k*10 + batch)
    __shared__ __align__(16) float sm[12288];

    const int tid  = threadIdx.x;
    const int bid  = blockIdx.x;
    const int gtid = bid * 512 + tid;
    const int nthr = GBLK * 512;
    const int w = tid >> 5, lane = tid & 31;

    float* wqs   = sm + 6144;   // [2][512]
    float* redct = sm;          // [2][4][516]
    float* vs    = sm + 4128;   // [512]
    float* es    = sm + 4640;   // [2][256]
    float* beta  = sm + 5152;   // [2][256]
    float* red8  = sm + 5664;   // [2][8]

    // ---------------- preamble ----------------
    for (int i = gtid; i < 524288; i += nthr) {            // W_d -> WdT[k][col]
        int n = i >> 10, j = i & 1023;
        g_WdT[j * 512 + n] = W_d[i];
    }
    for (int i = gtid; i < 262144; i += nthr) {            // U_d -> UdT[m][n]
        int n = i >> 9, m = i & 511;
        g_UdT[m * 512 + n] = U_d[i];
    }
    for (int i = gtid; i < 1048576; i += nthr) {           // W_ih/W_hh -> WT[k][g]
        int gcol = i >> 9, m = i & 511;
        g_WT[(size_t)m * 2048 + gcol] = W_ih[i];
        g_WT[(size_t)(512 + m) * 2048 + gcol] = W_hh[i];
    }
    for (int i = gtid; i < 2048; i += nthr)
        g_bias[i] = b_ih[i] + b_hh[i];
    for (int i = gtid; i < 8388608; i += nthr) {           // H -> fp16
        float4 h4 = *(const float4*)&H[(size_t)i * 4];
        *(__half2*)&g_Hh[(size_t)i * 4]     = __floats2half2_rn(h4.x, h4.y);
        *(__half2*)&g_Hh[(size_t)i * 4 + 2] = __floats2half2_rn(h4.z, h4.w);
    }
    gsync();

    // ---------------- phase U: UH = H @ UdT (fp16 out) ----------------
    for (int it = 0; it < 64; it++) {
        const int i0 = (bid * 64 + it) * 8;
        __syncthreads();
        for (int idx = tid; idx < 4096; idx += 512) {
            int m = idx & 511, r = idx >> 9;
            sm[m * 12 + r] = H[(size_t)(i0 + r) * 512 + m];
        }
        __syncthreads();

        unsigned long long acc[4] = {0, 0, 0, 0};
        const float* wcol = &g_UdT[tid];
#pragma unroll 4
        for (int m = 0; m < 512; m++) {
            unsigned long long w2 = pack2(wcol[m * 512]);
            const float* qr = &sm[m * 12];
            ulonglong2 q01 = *(const ulonglong2*)&qr[0];
            ulonglong2 q23 = *(const ulonglong2*)&qr[4];
            fma2(acc[0], w2, q01.x); fma2(acc[1], w2, q01.y);
            fma2(acc[2], w2, q23.x); fma2(acc[3], w2, q23.y);
        }
#pragma unroll
        for (int rp = 0; rp < 4; rp++) {
            float2 a = unpack2(acc[rp]);
            g_UHh[(size_t)(i0 + 2 * rp) * 512 + tid]     = __float2half_rn(a.x);
            g_UHh[(size_t)(i0 + 2 * rp + 1) * 512 + tid] = __float2half_rn(a.y);
        }
    }
    gsync();

    // ---------------- main scan: 256 steps, 2 barriers each ----------------
    for (int step = 0; step < 256; ++step) {
        const int b0 = bid * 2;

        // ======== fused P1+P2 (all data block-local) ========
        // -- LSTM state update for this step --
        {
            float dnew[2], snew[2];
            if (step == 0) {
#pragma unroll
                for (int r = 0; r < 2; r++) {
                    dnew[r] = d0[(b0 + r) * 512 + tid];
                    snew[r] = s0[(b0 + r) * 512 + tid];
                }
            } else {
#pragma unroll
                for (int r = 0; r < 2; r++) {
                    const int b = b0 + r;
                    const float* gr = &g_gates[b * 2048];
                    float gi = gr[tid]        + g_bias[tid];
                    float gf = gr[512 + tid]  + g_bias[512 + tid];
                    float gg = gr[1024 + tid] + g_bias[1024 + tid];
                    float go = gr[1536 + tid] + g_bias[1536 + tid];
                    float s_new = sigmoid_fast(gf) * g_s[b * 512 + tid]
                                + sigmoid_fast(gi) * tanh_fast(gg);
                    snew[r] = s_new;
                    dnew[r] = sigmoid_fast(go) * tanh_fast(s_new);
                }
            }
#pragma unroll
            for (int r = 0; r < 2; r++) {
                sm[tid * 2 + r]         = dnew[r];          // q[k<512]  = d
                sm[(512 + tid) * 2 + r] = snew[r];          // q[k>=512] = s
                g_d[(b0 + r) * 512 + tid] = dnew[r];
                g_s[(b0 + r) * 512 + tid] = snew[r];
            }
            __syncthreads();

            // -- wq GEMM: thread = (ks = tid>>7, 4 cols at (tid&127)*4) --
            const int cthr = tid & 127, ks = tid >> 7;
            const int col = cthr * 4;
            unsigned long long acc[4] = {0, 0, 0, 0};
            const float* wbase = &g_WdT[(ks * 256) * 512 + col];
            const float* qbase = &sm[(ks * 256) * 2];
#pragma unroll 4
            for (int kk = 0; kk < 256; kk++) {
                float4 w4 = *(const float4*)&wbase[kk * 512];
                unsigned long long q2 = *(const unsigned long long*)&qbase[kk * 2];
                fma2(acc[0], pack2(w4.x), q2);
                fma2(acc[1], pack2(w4.y), q2);
                fma2(acc[2], pack2(w4.z), q2);
                fma2(acc[3], pack2(w4.w), q2);
            }
            __syncthreads();
#pragma unroll
            for (int c = 0; c < 4; c++)
                *(unsigned long long*)&sm[2048 + (ks * 512 + col + c) * 2] = acc[c];
            __syncthreads();
            // reduce over 4 k-slices; write wqs[b][col]
            {
                float2 rr = make_float2(0.f, 0.f);
#pragma unroll
                for (int k2 = 0; k2 < 4; k2++) {
                    float2 p = *(const float2*)&sm[2048 + (k2 * 512 + tid) * 2];
                    rr.x += p.x; rr.y += p.y;
                }
                wqs[tid]       = rr.x;   // batch b0
                wqs[512 + tid] = rr.y;   // batch b0+1
                vs[tid & 511]  = v_d[tid & 511];
            }
            __syncthreads();
        }

        // -- e-pass: warps 0-7 -> batch 0, warps 8-15 -> batch 1; 32 t-rows/warp --
        {
            const int b = w >> 3, wb = w & 7;
            const int t0 = wb * 32;
            const float* wqb = wqs + b * 512;
            const float* wq8a = wqb + lane * 8;
            const float* wq8b = wqb + 256 + lane * 8;
            const float* v8a = vs + lane * 8;
            const float* v8b = vs + 256 + lane * 8;
            const __half* pb = g_UHh + ((size_t)(b0 + b) * 256 + t0) * 512 + lane * 8;
#pragma unroll 2
            for (int grp = 0; grp < 8; grp++) {
                const __half* p = pb + (size_t)grp * 2048;
                uint4 u0 = *(const uint4*)p;
                uint4 u1 = *(const uint4*)(p + 256);
                uint4 u2 = *(const uint4*)(p + 512);
                uint4 u3 = *(const uint4*)(p + 768);
                uint4 u4 = *(const uint4*)(p + 1024);
                uint4 u5 = *(const uint4*)(p + 1280);
                uint4 u6 = *(const uint4*)(p + 1536);
                uint4 u7 = *(const uint4*)(p + 1792);
                float a0 = row_term(u0, wq8a, v8a) + row_term(u1, wq8b, v8b);
                float a1 = row_term(u2, wq8a, v8a) + row_term(u3, wq8b, v8b);
                float a2 = row_term(u4, wq8a, v8a) + row_term(u5, wq8b, v8b);
                float a3 = row_term(u6, wq8a, v8a) + row_term(u7, wq8b, v8b);
#pragma unroll
                for (int off = 16; off; off >>= 1) {
                    a0 += __shfl_xor_sync(0xffffffffu, a0, off);
                    a1 += __shfl_xor_sync(0xffffffffu, a1, off);
                    a2 += __shfl_xor_sync(0xffffffffu, a2, off);
                    a3 += __shfl_xor_sync(0xffffffffu, a3, off);
                }
                if (lane == 0) {
                    float* ep = &es[b * 256 + t0 + grp * 4];
                    ep[0] = a0; ep[1] = a1; ep[2] = a2; ep[3] = a3;
                }
            }
        }
        __syncthreads();

        // -- softmax (both batches concurrently) + attn write --
        {
            const int b2 = tid >> 8, tt = tid & 255, wbt = (tid >> 5) & 7;
            float ev = es[b2 * 256 + tt];
            float mv = ev;
#pragma unroll
            for (int off = 16; off; off >>= 1)
                mv = fmaxf(mv, __shfl_xor_sync(0xffffffffu, mv, off));
            if (lane == 0) red8[b2 * 8 + wbt] = mv;
            __syncthreads();
            float bm = red8[b2 * 8];
#pragma unroll
            for (int i = 1; i < 8; i++) bm = fmaxf(bm, red8[b2 * 8 + i]);
            float ex = __expf(ev - bm);
            float sv = ex;
#pragma unroll
            for (int off = 16; off; off >>= 1)
                sv += __shfl_xor_sync(0xffffffffu, sv, off);
            __syncthreads();                       // all reads of red8 (max) done
            if (lane == 0) red8[b2 * 8 + wbt] = sv;
            __syncthreads();
            float bs = 0.f;
#pragma unroll
            for (int i = 0; i < 8; i++) bs += red8[b2 * 8 + i];
            float bt = ex / bs;
            beta[b2 * 256 + tt] = bt;
            out[(size_t)ATTN_OFF + (size_t)(b0 + b2) * 65536
                + (size_t)step * 256 + tt] = bt;
        }
        __syncthreads();

        // -- ct: thread = (b2 = tid>>8, c = 8 cols, tg = 64-t group), deep MLP --
        {
            const int b2 = tid >> 8, r = tid & 255;
            const int c = r & 63, tg = r >> 6;
            const float* bp = &beta[b2 * 256 + tg * 64];
            const __half* hp = g_Hh + (size_t)(b0 + b2) * 131072
                               + (size_t)(tg * 64) * 512 + c * 8;
            float f[8] = {0.f, 0.f, 0.f, 0.f, 0.f, 0.f, 0.f, 0.f};
#pragma unroll 1
            for (int i8 = 0; i8 < 8; i8++) {
                uint4 hv[8];
#pragma unroll
                for (int j = 0; j < 8; j++)
                    hv[j] = *(const uint4*)(hp + (size_t)j * 512);
#pragma unroll
                for (int j = 0; j < 8; j++) {
                    float bv = bp[i8 * 8 + j];
                    float2 h0 = __half22float2(*(__half2*)&hv[j].x);
                    float2 h1 = __half22float2(*(__half2*)&hv[j].y);
                    float2 h2 = __half22float2(*(__half2*)&hv[j].z);
                    float2 h3 = __half22float2(*(__half2*)&hv[j].w);
                    f[0] += bv * h0.x; f[1] += bv * h0.y;
                    f[2] += bv * h1.x; f[3] += bv * h1.y;
                    f[4] += bv * h2.x; f[5] += bv * h2.y;
                    f[6] += bv * h3.x; f[7] += bv * h3.y;
                }
                hp += 4096;
            }
            float* rc = &redct[((b2 * 4 + tg) * 516) + c * 8];
            *(float4*)&rc[0] = make_float4(f[0], f[1], f[2], f[3]);
            *(float4*)&rc[4] = make_float4(f[4], f[5], f[6], f[7]);
        }
        __syncthreads();
        {
#pragma unroll
            for (int j = 0; j < 2; j++) {
                int idx = tid * 2 + j;
                int b3 = idx >> 9, col = idx & 511;
                float s = redct[(b3 * 4 + 0) * 516 + col]
                        + redct[(b3 * 4 + 1) * 516 + col]
                        + redct[(b3 * 4 + 2) * 516 + col]
                        + redct[(b3 * 4 + 3) * 516 + col];
                g_ct[(b0 + b3) * 512 + col] = s;
            }
        }
        gsync();

        // ======== P3: gates GEMM, tile = 8 batches x 512 cols, full K ========
        {
            const int gb0 = (bid >> 2) * 8;
            const int cg = bid & 3;
            for (int idx = tid; idx < 8192; idx += 512) {     // sm[k*10 + batch]
                int k = idx & 1023, r = idx >> 10;
                float v = (k < 512) ? g_ct[(gb0 + r) * 512 + k]
                                    : g_d[(gb0 + r) * 512 + (k - 512)];
                sm[k * 10 + r] = v;
            }
            __syncthreads();

            const int cthr = tid & 127, bp = tid >> 7;       // 4 cols, 1 batch-pair
            const int col = cg * 512 + cthr * 4;
            unsigned long long acc[4] = {0, 0, 0, 0};
            const float* wbase = &g_WT[col];
            const float* qbase = &sm[bp * 2];
#pragma unroll 4
            for (int k = 0; k < 1024; k++) {
                float4 w4 = *(const float4*)&wbase[(size_t)k * 2048];
                unsigned long long q2 = *(const unsigned long long*)&qbase[k * 10];
                fma2(acc[0], pack2(w4.x), q2);
                fma2(acc[1], pack2(w4.y), q2);
                fma2(acc[2], pack2(w4.z), q2);
                fma2(acc[3], pack2(w4.w), q2);
            }
            const int ba = gb0 + 2 * bp;
            float4 lo, hi;
            {
                float2 a0 = unpack2(acc[0]), a1 = unpack2(acc[1]);
                float2 a2 = unpack2(acc[2]), a3 = unpack2(acc[3]);
                lo = make_float4(a0.x, a1.x, a2.x, a3.x);
                hi = make_float4(a0.y, a1.y, a2.y, a3.y);
            }
            *(float4*)&g_gates[(size_t)ba * 2048 + col]       = lo;
            *(float4*)&g_gates[(size_t)(ba + 1) * 2048 + col] = hi;
        }
        gsync();
    }

    // ---------------- epilogue: final LSTM -> out head [d_final ; ct_last] ----------------
    for (int idx = gtid; idx < 131072; idx += nthr) {
        const int b = idx >> 9, p = idx & 511;
        const float* gr = &g_gates[b * 2048];
        float gi = gr[p]        + g_bias[p];
        float gf = gr[512 + p]  + g_bias[512 + p];
        float gg = gr[1024 + p] + g_bias[1024 + p];
        float go = gr[1536 + p] + g_bias[1536 + p];
        float s_new = sigmoid_fast(gf) * g_s[idx] + sigmoid_fast(gi) * tanh_fast(gg);
        float d_new = sigmoid_fast(go) * tanh_fast(s_new);
        out[b * 1024 + p]       = d_new;
        out[b * 1024 + 512 + p] = g_ct[idx];
    }
}

// ------------------- launch -------------------
extern "C" void kernel_launch(void* const* d_in, const int* in_sizes, int n_in,
                              void* d_out, int out_size) {
    (void)in_sizes; (void)n_in; (void)out_size;
    const float* H    = (const float*)d_in[0];
    const float* d0   = (const float*)d_in[1];
    const float* s0   = (const float*)d_in[2];
    const float* W_d  = (const float*)d_in[3];
    const float* U_d  = (const float*)d_in[4];
    const float* v_d  = (const float*)d_in[5];
    const float* W_ih = (const float*)d_in[6];
    const float* W_hh = (const float*)d_in[7];
    const float* b_ih = (const float*)d_in[8];
    const float* b_hh = (const float*)d_in[9];
    float* out = (float*)d_out;

    k_decoder<<<GBLK, 512>>>(H, d0, s0, W_d, U_d, v_d, W_ih, W_hh, b_ih, b_hh, out);
}